// round 7
// baseline (speedup 1.0000x reference)
#include <cuda_runtime.h>
#include <cuda_fp16.h>

#define NN 4096
#define FIN 128
#define FOUT 64
#define HEADS 4
#define MSPLIT 4
#define RPB 128          // n-rows per block in k_attn
#define MTILE 128        // m per smem tile

// Device scratch (allocation-free rule: __device__ globals)
__device__ unsigned g_H2[HEADS * (NN / 2) * FOUT];   // H pairs (2m,2m+1) as fp16x2
__device__ float2   g_EF[HEADS * NN];                // {exp(d), exp(0.01d)}
__device__ float    g_G[HEADS * NN];                 // exp(-0.99 s)
__device__ unsigned g_mask[NN * (NN / 32)];          // bit-packed A|diag, MMA-permuted
__device__ unsigned g_numh[HEADS * MSPLIT * NN * (FOUT / 2)];  // fp16x2, scaled 1/32
__device__ float    g_l[HEADS * MSPLIT * NN];

__device__ __forceinline__ unsigned hmul2u(unsigned a, unsigned b) {
    __half2 r = __hmul2(*(__half2*)&a, *(__half2*)&b);
    return *(unsigned*)&r;
}
__device__ __forceinline__ unsigned hmax2u(unsigned a, unsigned b) {
    __half2 r = __hmax2(*(__half2*)&a, *(__half2*)&b);
    return *(unsigned*)&r;
}
__device__ __forceinline__ unsigned pk2(float lo, float hi) {
    __half2 r = __floats2half2_rn(lo, hi);
    return *(unsigned*)&r;
}

__device__ __forceinline__ void mma_f16(float c[4], const unsigned a[4],
                                        unsigned b0, unsigned b1) {
    asm volatile(
        "mma.sync.aligned.m16n8k16.row.col.f32.f16.f16.f32 "
        "{%0,%1,%2,%3}, {%4,%5,%6,%7}, {%8,%9}, {%0,%1,%2,%3};\n"
        : "+f"(c[0]), "+f"(c[1]), "+f"(c[2]), "+f"(c[3])
        : "r"(a[0]), "r"(a[1]), "r"(a[2]), "r"(a[3]), "r"(b0), "r"(b1));
}

// ---------------------------------------------------------------------------
// Kernel 1: merged projection (blocks 0..255) + adjacency bit-pack (blocks
// 256..4351). Overlaps DRAM-bound pack with compute-bound proj.
// ---------------------------------------------------------------------------
__global__ void __launch_bounds__(256) k_pp(const int* __restrict__ A,
                                            const float* __restrict__ X,
                                            const float* __restrict__ W,
                                            const float* __restrict__ b,
                                            const float* __restrict__ att) {
    __shared__ __align__(16) float Xs[64][68];
    __shared__ __align__(16) float Ws[64][68];
    const int t = threadIdx.x;

    if (blockIdx.x >= 256) {
        // ---- pack: bits PRE-PERMUTED into MMA nibble order:
        // word bit (16hh+4tt+dd) = adjacency col (16hh + 2tt + (dd&1) + (dd>>1)*8)
        const int row  = blockIdx.x - 256;
        const int warp = t >> 5, lane = t & 31;
        const int hh = (lane >> 4) & 1, tt = (lane >> 2) & 3, dd = lane & 3;
        const int off = 16 * hh + 2 * tt + (dd & 1) + ((dd >> 1) << 3);
        const int* Arow = A + row * NN;
#pragma unroll
        for (int c = warp; c < NN / 32; c += 8) {
            int col = c * 32 + off;
            int a = Arow[col];
            unsigned m = __ballot_sync(0xffffffffu, (a > 0) || (col == row));
            if (lane == 0) g_mask[row * (NN / 32) + c] = m;
        }
        return;
    }

    // ---- projection + fused per-node scores/exp factors
    const int h  = blockIdx.x >> 6;
    const int n0 = (blockIdx.x & 63) * 64;
    const int ty = t >> 4, tx = t & 15;

    float acc[4][4] = {};

    for (int kc = 0; kc < FIN; kc += 64) {
        __syncthreads();
#pragma unroll
        for (int u = 0; u < 4; u++) {
            int idx = t + 256 * u;
            int r = idx >> 4, q = (idx & 15) * 4;
            float4 xv = *(const float4*)&X[(n0 + r) * FIN + kc + q];
            Xs[r][q] = xv.x; Xs[r][q + 1] = xv.y; Xs[r][q + 2] = xv.z; Xs[r][q + 3] = xv.w;
            float4 wv = *(const float4*)&W[(h * FOUT + r) * FIN + kc + q];
            Ws[r][q] = wv.x; Ws[r][q + 1] = wv.y; Ws[r][q + 2] = wv.z; Ws[r][q + 3] = wv.w;
        }
        __syncthreads();
#pragma unroll 8
        for (int k = 0; k < 64; k++) {
            float a0 = Xs[ty * 4 + 0][k], a1 = Xs[ty * 4 + 1][k];
            float a2 = Xs[ty * 4 + 2][k], a3 = Xs[ty * 4 + 3][k];
            float b0 = Ws[tx * 4 + 0][k], b1 = Ws[tx * 4 + 1][k];
            float b2 = Ws[tx * 4 + 2][k], b3 = Ws[tx * 4 + 3][k];
            acc[0][0] += a0 * b0; acc[0][1] += a0 * b1; acc[0][2] += a0 * b2; acc[0][3] += a0 * b3;
            acc[1][0] += a1 * b0; acc[1][1] += a1 * b1; acc[1][2] += a1 * b2; acc[1][3] += a1 * b3;
            acc[2][0] += a2 * b0; acc[2][1] += a2 * b1; acc[2][2] += a2 * b2; acc[2][3] += a2 * b3;
            acc[3][0] += a3 * b0; acc[3][1] += a3 * b1; acc[3][2] += a3 * b2; acc[3][3] += a3 * b3;
        }
    }

    float bb[4], as4[4], ad4[4];
#pragma unroll
    for (int j = 0; j < 4; j++) {
        bb[j]  = b[h * FOUT + tx * 4 + j];
        as4[j] = att[h * 2 * FOUT + tx * 4 + j];
        ad4[j] = att[h * 2 * FOUT + FOUT + tx * 4 + j];
    }
    float hv[4][4];
#pragma unroll
    for (int i = 0; i < 4; i++) {
        int n = n0 + ty * 4 + i;
        float s = 0.f, d = 0.f;
#pragma unroll
        for (int j = 0; j < 4; j++) {
            hv[i][j] = acc[i][j] + bb[j];
            s += hv[i][j] * as4[j];
            d += hv[i][j] * ad4[j];
        }
#pragma unroll
        for (int off = 8; off > 0; off >>= 1) {
            s += __shfl_xor_sync(0xffffffffu, s, off);
            d += __shfl_xor_sync(0xffffffffu, d, off);
        }
        if (tx == 0) {
            g_EF[h * NN + n] = make_float2(__expf(d), __expf(0.01f * d));
            g_G[h * NN + n]  = __expf(-0.99f * s);
        }
    }
    // write H as pair-packed fp16x2: g_H2[h][n/2][col]
#pragma unroll
    for (int i = 0; i < 4; i += 2) {
        int np = (n0 + ty * 4 + i) >> 1;
        uint4 pk = make_uint4(pk2(hv[i][0], hv[i + 1][0]), pk2(hv[i][1], hv[i + 1][1]),
                              pk2(hv[i][2], hv[i + 1][2]), pk2(hv[i][3], hv[i + 1][3]));
        *(uint4*)&g_H2[(h * (NN / 2) + np) * FOUT + tx * 4] = pk;
    }
}

// ---------------------------------------------------------------------------
// Kernel 2: fp16 tensor-core PV.  p = adj * max(E_m, F_m*G_n)  (exact
// leaky_relu branch select). l via ones-column MMA.
// block = 256 thr (8 warps x 16 rows); grid (32, MSPLIT, HEADS)
// ---------------------------------------------------------------------------
__global__ void __launch_bounds__(256) k_attn() {
    __shared__ unsigned Hs2[MTILE / 2][72];     // H pairs as fp16x2
    __shared__ uint2    dEF2s[MTILE / 2];       // {E2, F2} fp16x2 pairs
    __shared__ unsigned maskS[RPB][MTILE / 32];

    const int h  = blockIdx.z;
    const int sp = blockIdx.y;
    const int n0 = blockIdx.x * RPB;
    const int t  = threadIdx.x;
    const int warp = t >> 5, lane = t & 31;
    const int g = lane >> 2, tt = lane & 3;
    const int wrow = warp * 16;
    const unsigned ONES2 = 0x3C003C00u;

    unsigned G2u[2];
#pragma unroll
    for (int j = 0; j < 2; j++) {
        float gv = g_G[h * NN + n0 + wrow + g + 8 * j];
        G2u[j] = pk2(gv, gv);
    }

    float cacc[8][4] = {};
    float lacc[4] = {0.f, 0.f, 0.f, 0.f};

    const int mbase = sp * (NN / MSPLIT);

    for (int mt = 0; mt < NN / MSPLIT; mt += MTILE) {
        const int mb = mbase + mt;
        __syncthreads();
#pragma unroll
        for (int u = 0; u < 4; u++) {
            int id = t + 256 * u;
            int mp = id >> 4, q = (id & 15) << 2;
            *(uint4*)&Hs2[mp][q] =
                *(const uint4*)&g_H2[(h * (NN / 2) + (mb >> 1) + mp) * FOUT + q];
        }
        if (t < 64) {
            float2 v0 = g_EF[h * NN + mb + 2 * t];
            float2 v1 = g_EF[h * NN + mb + 2 * t + 1];
            dEF2s[t] = make_uint2(pk2(v0.x, v1.x), pk2(v0.y, v1.y));
        }
        if (t < RPB)
            *(uint4*)&maskS[t][0] =
                *(const uint4*)&g_mask[(n0 + t) * (NN / 32) + (mb >> 5)];
        __syncthreads();

#pragma unroll
        for (int cc = 0; cc < 8; cc++) {
            const uint2 ef0 = dEF2s[cc * 8 + tt];
            const uint2 ef1 = dEF2s[cc * 8 + tt + 4];
            unsigned pa[4];
#pragma unroll
            for (int j = 0; j < 2; j++) {
                unsigned w = maskS[wrow + g + 8 * j][cc >> 1];
                unsigned nib = (w >> (((cc & 1) << 4) + (tt << 2))) & 0xFu;
                unsigned am0 = (nib & 1u) * 0x3C00u + (nib & 2u) * 0x1E000000u;
                unsigned am1 = (nib & 4u) * 0x0F00u + (nib & 8u) * 0x07800000u;
                pa[j]     = hmul2u(hmax2u(ef0.x, hmul2u(ef0.y, G2u[j])), am0);
                pa[2 + j] = hmul2u(hmax2u(ef1.x, hmul2u(ef1.y, G2u[j])), am1);
            }
#pragma unroll
            for (int jc = 0; jc < 8; jc++) {
                unsigned b0 = Hs2[cc * 8 + tt][jc * 8 + g];
                unsigned b1 = Hs2[cc * 8 + tt + 4][jc * 8 + g];
                mma_f16(cacc[jc], pa, b0, b1);
            }
            mma_f16(lacc, pa, ONES2, ONES2);
        }
    }

    const int base = (h * MSPLIT + sp) * NN;
    if (tt == 0) {
        g_l[base + n0 + wrow + g]     = lacc[0];
        g_l[base + n0 + wrow + g + 8] = lacc[2];
    }
    const float S = 1.0f / 32.0f;
    const int r0 = base + n0 + wrow + g;
#pragma unroll
    for (int jc = 0; jc < 8; jc++) {
        g_numh[r0 * (FOUT / 2) + jc * 4 + tt] = pk2(cacc[jc][0] * S, cacc[jc][1] * S);
        g_numh[(r0 + 8) * (FOUT / 2) + jc * 4 + tt] = pk2(cacc[jc][2] * S, cacc[jc][3] * S);
    }
}

// ---------------------------------------------------------------------------
// Kernel 3: combine m-splits and heads: out = 0.25 * sum_h 32*(sum_sp num)/(sum_sp l)
// ---------------------------------------------------------------------------
__global__ void k_comb(float* __restrict__ out) {
    const int t = blockIdx.x * 256 + threadIdx.x;
    const int n = t >> 4;
    const int qc = t & 15;            // 4-col group
    float4 r = make_float4(0.f, 0.f, 0.f, 0.f);
#pragma unroll
    for (int h = 0; h < HEADS; h++) {
        float l = 0.0f;
        float4 acc = make_float4(0.f, 0.f, 0.f, 0.f);
#pragma unroll
        for (int sp = 0; sp < MSPLIT; sp++) {
            const int row = (h * MSPLIT + sp) * NN + n;
            l += g_l[row];
            uint2 v = *(const uint2*)&g_numh[row * (FOUT / 2) + qc * 2];
            float2 lo = __half22float2(*(__half2*)&v.x);
            float2 hi = __half22float2(*(__half2*)&v.y);
            acc.x += lo.x; acc.y += lo.y; acc.z += hi.x; acc.w += hi.y;
        }
        float inv = 32.0f / l;
        r.x += acc.x * inv; r.y += acc.y * inv; r.z += acc.z * inv; r.w += acc.w * inv;
    }
    r.x *= 0.25f; r.y *= 0.25f; r.z *= 0.25f; r.w *= 0.25f;
    *(float4*)&out[n * FOUT + qc * 4] = r;
}

extern "C" void kernel_launch(void* const* d_in, const int* in_sizes, int n_in,
                              void* d_out, int out_size) {
    const float* X   = (const float*)d_in[0];
    const int*   A   = (const int*)d_in[1];
    const float* W   = (const float*)d_in[2];
    const float* b   = (const float*)d_in[3];
    const float* att = (const float*)d_in[4];
    float* out = (float*)d_out;

    k_pp<<<256 + NN, 256>>>(A, X, W, b, att);
    k_attn<<<dim3(NN / RPB, MSPLIT, HEADS), 256>>>();
    k_comb<<<(NN * FOUT / 4) / 256, 256>>>(out);
}

// round 8
// speedup vs baseline: 1.0724x; 1.0724x over previous
#include <cuda_runtime.h>
#include <cuda_fp16.h>

#define NN 4096
#define FIN 128
#define FOUT 64
#define HEADS 4
#define MSPLIT 4
#define RPB 128          // n-rows per block in k_attn
#define MTILE 128        // m per smem tile

// Device scratch (allocation-free rule: __device__ globals)
__device__ unsigned g_H2[HEADS * (NN / 2) * FOUT];   // H pairs (2m,2m+1) as fp16x2
__device__ float2   g_EF[HEADS * NN];                // {exp(d), exp(0.01d)}
__device__ float    g_G[HEADS * NN];                 // exp(-0.99 s)
__device__ unsigned g_mask[NN * (NN / 32)];          // bit-packed A|diag, MMA-permuted
__device__ unsigned g_numh[HEADS * MSPLIT * NN * (FOUT / 2)];  // fp16x2, scaled 1/32
__device__ float    g_l[HEADS * MSPLIT * NN];

__device__ __forceinline__ unsigned hmul2u(unsigned a, unsigned b) {
    __half2 r = __hmul2(*(__half2*)&a, *(__half2*)&b);
    return *(unsigned*)&r;
}
__device__ __forceinline__ unsigned hmax2u(unsigned a, unsigned b) {
    __half2 r = __hmax2(*(__half2*)&a, *(__half2*)&b);
    return *(unsigned*)&r;
}
__device__ __forceinline__ unsigned pk2(float lo, float hi) {
    __half2 r = __floats2half2_rn(lo, hi);
    return *(unsigned*)&r;
}

__device__ __forceinline__ void mma_f16(float c[4], const unsigned a[4],
                                        unsigned b0, unsigned b1) {
    asm volatile(
        "mma.sync.aligned.m16n8k16.row.col.f32.f16.f16.f32 "
        "{%0,%1,%2,%3}, {%4,%5,%6,%7}, {%8,%9}, {%0,%1,%2,%3};\n"
        : "+f"(c[0]), "+f"(c[1]), "+f"(c[2]), "+f"(c[3])
        : "r"(a[0]), "r"(a[1]), "r"(a[2]), "r"(a[3]), "r"(b0), "r"(b1));
}

// ---------------------------------------------------------------------------
// Kernel 1: merged projection (blocks 0..255) + adjacency bit-pack (blocks
// 256..). Pack builds each mask word in-register (no ballot): thread owns one
// 32-bit word, 8 independent LDG.128, permuted bit position computed at
// compile time. Proj uses TRANSPOSED smem tiles -> conflict-free LDS.128.
// ---------------------------------------------------------------------------
__global__ void __launch_bounds__(256) k_pp(const int* __restrict__ A,
                                            const float* __restrict__ X,
                                            const float* __restrict__ W,
                                            const float* __restrict__ b,
                                            const float* __restrict__ att) {
    __shared__ __align__(16) float XsT[64][68];   // [k][n-row]
    __shared__ __align__(16) float WsT[64][68];   // [k][o-row]
    const int t = threadIdx.x;

    if (blockIdx.x >= 256) {
        // ---- pack: word bit (16hh+4tt+dd) = adjacency col (16hh+2tt+(dd&1)+8*(dd>>1))
        const int row = (blockIdx.x - 256) * 2 + (t >> 7);
        const int c   = t & 127;                   // word index (32 cols)
        const int4* Ar = (const int4*)(A + row * NN + c * 32);
        unsigned word = 0;
#pragma unroll
        for (int i = 0; i < 8; i++) {
            int4 a4 = Ar[i];
            int av[4] = { a4.x, a4.y, a4.z, a4.w };
#pragma unroll
            for (int q = 0; q < 4; q++) {
                const int colw = i * 4 + q;
                const int l4 = colw & 15;
                const int bp = ((colw >> 4) << 4) + (((l4 >> 1) & 3) << 2)
                             + (l4 & 1) + ((l4 >> 3) << 1);
                const int colg = c * 32 + colw;
                unsigned pred = (av[q] > 0) || (colg == row);
                word |= pred << bp;
            }
        }
        g_mask[row * (NN / 32) + c] = word;
        return;
    }

    // ---- projection + fused per-node scores/exp factors
    const int h  = blockIdx.x >> 6;
    const int n0 = (blockIdx.x & 63) * 64;
    const int ty = t >> 4, tx = t & 15;

    float acc[4][4] = {};

    for (int kc = 0; kc < FIN; kc += 64) {
        __syncthreads();
#pragma unroll
        for (int u = 0; u < 4; u++) {
            int idx = t + 256 * u;
            int r = idx >> 4, q = (idx & 15) * 4;
            float4 xv = *(const float4*)&X[(n0 + r) * FIN + kc + q];
            XsT[q + 0][r] = xv.x; XsT[q + 1][r] = xv.y;
            XsT[q + 2][r] = xv.z; XsT[q + 3][r] = xv.w;
            float4 wv = *(const float4*)&W[(h * FOUT + r) * FIN + kc + q];
            WsT[q + 0][r] = wv.x; WsT[q + 1][r] = wv.y;
            WsT[q + 2][r] = wv.z; WsT[q + 3][r] = wv.w;
        }
        __syncthreads();
#pragma unroll 8
        for (int k = 0; k < 64; k++) {
            float4 av = *(const float4*)&XsT[k][ty * 4];
            float4 bv = *(const float4*)&WsT[k][tx * 4];
            acc[0][0] += av.x * bv.x; acc[0][1] += av.x * bv.y; acc[0][2] += av.x * bv.z; acc[0][3] += av.x * bv.w;
            acc[1][0] += av.y * bv.x; acc[1][1] += av.y * bv.y; acc[1][2] += av.y * bv.z; acc[1][3] += av.y * bv.w;
            acc[2][0] += av.z * bv.x; acc[2][1] += av.z * bv.y; acc[2][2] += av.z * bv.z; acc[2][3] += av.z * bv.w;
            acc[3][0] += av.w * bv.x; acc[3][1] += av.w * bv.y; acc[3][2] += av.w * bv.z; acc[3][3] += av.w * bv.w;
        }
    }

    float bb[4], as4[4], ad4[4];
#pragma unroll
    for (int j = 0; j < 4; j++) {
        bb[j]  = b[h * FOUT + tx * 4 + j];
        as4[j] = att[h * 2 * FOUT + tx * 4 + j];
        ad4[j] = att[h * 2 * FOUT + FOUT + tx * 4 + j];
    }
    float hv[4][4];
#pragma unroll
    for (int i = 0; i < 4; i++) {
        int n = n0 + ty * 4 + i;
        float s = 0.f, d = 0.f;
#pragma unroll
        for (int j = 0; j < 4; j++) {
            hv[i][j] = acc[i][j] + bb[j];
            s += hv[i][j] * as4[j];
            d += hv[i][j] * ad4[j];
        }
#pragma unroll
        for (int off = 8; off > 0; off >>= 1) {
            s += __shfl_xor_sync(0xffffffffu, s, off);
            d += __shfl_xor_sync(0xffffffffu, d, off);
        }
        if (tx == 0) {
            g_EF[h * NN + n] = make_float2(__expf(d), __expf(0.01f * d));
            g_G[h * NN + n]  = __expf(-0.99f * s);
        }
    }
    // write H as pair-packed fp16x2: g_H2[h][n/2][col]
#pragma unroll
    for (int i = 0; i < 4; i += 2) {
        int np = (n0 + ty * 4 + i) >> 1;
        uint4 pk = make_uint4(pk2(hv[i][0], hv[i + 1][0]), pk2(hv[i][1], hv[i + 1][1]),
                              pk2(hv[i][2], hv[i + 1][2]), pk2(hv[i][3], hv[i + 1][3]));
        *(uint4*)&g_H2[(h * (NN / 2) + np) * FOUT + tx * 4] = pk;
    }
}

// ---------------------------------------------------------------------------
// Kernel 2: fp16 tensor-core PV.  p = adj * max(E_m, F_m*G_n)  (exact
// leaky_relu branch select). l via ones-column MMA.
// block = 256 thr (8 warps x 16 rows); grid (32, MSPLIT, HEADS)
// ---------------------------------------------------------------------------
__global__ void __launch_bounds__(256) k_attn() {
    __shared__ unsigned Hs2[MTILE / 2][72];     // H pairs as fp16x2
    __shared__ uint2    dEF2s[MTILE / 2];       // {E2, F2} fp16x2 pairs
    __shared__ unsigned maskS[RPB][MTILE / 32];

    const int h  = blockIdx.z;
    const int sp = blockIdx.y;
    const int n0 = blockIdx.x * RPB;
    const int t  = threadIdx.x;
    const int warp = t >> 5, lane = t & 31;
    const int g = lane >> 2, tt = lane & 3;
    const int wrow = warp * 16;
    const unsigned ONES2 = 0x3C003C00u;

    unsigned G2u[2];
#pragma unroll
    for (int j = 0; j < 2; j++) {
        float gv = g_G[h * NN + n0 + wrow + g + 8 * j];
        G2u[j] = pk2(gv, gv);
    }

    float cacc[8][4] = {};
    float lacc[4] = {0.f, 0.f, 0.f, 0.f};

    const int mbase = sp * (NN / MSPLIT);

    for (int mt = 0; mt < NN / MSPLIT; mt += MTILE) {
        const int mb = mbase + mt;
        __syncthreads();
#pragma unroll
        for (int u = 0; u < 4; u++) {
            int id = t + 256 * u;
            int mp = id >> 4, q = (id & 15) << 2;
            *(uint4*)&Hs2[mp][q] =
                *(const uint4*)&g_H2[(h * (NN / 2) + (mb >> 1) + mp) * FOUT + q];
        }
        if (t < 64) {
            float2 v0 = g_EF[h * NN + mb + 2 * t];
            float2 v1 = g_EF[h * NN + mb + 2 * t + 1];
            dEF2s[t] = make_uint2(pk2(v0.x, v1.x), pk2(v0.y, v1.y));
        }
        if (t < RPB)
            *(uint4*)&maskS[t][0] =
                *(const uint4*)&g_mask[(n0 + t) * (NN / 32) + (mb >> 5)];
        __syncthreads();

#pragma unroll
        for (int cc = 0; cc < 8; cc++) {
            const uint2 ef0 = dEF2s[cc * 8 + tt];
            const uint2 ef1 = dEF2s[cc * 8 + tt + 4];
            unsigned pa[4];
#pragma unroll
            for (int j = 0; j < 2; j++) {
                unsigned w = maskS[wrow + g + 8 * j][cc >> 1];
                unsigned nib = (w >> (((cc & 1) << 4) + (tt << 2))) & 0xFu;
                unsigned am0 = (nib & 1u) * 0x3C00u + (nib & 2u) * 0x1E000000u;
                unsigned am1 = (nib & 4u) * 0x0F00u + (nib & 8u) * 0x07800000u;
                pa[j]     = hmul2u(hmax2u(ef0.x, hmul2u(ef0.y, G2u[j])), am0);
                pa[2 + j] = hmul2u(hmax2u(ef1.x, hmul2u(ef1.y, G2u[j])), am1);
            }
#pragma unroll
            for (int jc = 0; jc < 8; jc++) {
                unsigned b0 = Hs2[cc * 8 + tt][jc * 8 + g];
                unsigned b1 = Hs2[cc * 8 + tt + 4][jc * 8 + g];
                mma_f16(cacc[jc], pa, b0, b1);
            }
            mma_f16(lacc, pa, ONES2, ONES2);
        }
    }

    const int base = (h * MSPLIT + sp) * NN;
    if (tt == 0) {
        g_l[base + n0 + wrow + g]     = lacc[0];
        g_l[base + n0 + wrow + g + 8] = lacc[2];
    }
    const float S = 1.0f / 32.0f;
    const int r0 = base + n0 + wrow + g;
#pragma unroll
    for (int jc = 0; jc < 8; jc++) {
        g_numh[r0 * (FOUT / 2) + jc * 4 + tt] = pk2(cacc[jc][0] * S, cacc[jc][1] * S);
        g_numh[(r0 + 8) * (FOUT / 2) + jc * 4 + tt] = pk2(cacc[jc][2] * S, cacc[jc][3] * S);
    }
}

// ---------------------------------------------------------------------------
// Kernel 3: combine m-splits and heads
// ---------------------------------------------------------------------------
__global__ void k_comb(float* __restrict__ out) {
    const int t = blockIdx.x * 256 + threadIdx.x;
    const int n = t >> 4;
    const int qc = t & 15;
    float4 r = make_float4(0.f, 0.f, 0.f, 0.f);
#pragma unroll
    for (int h = 0; h < HEADS; h++) {
        float l = 0.0f;
        float4 acc = make_float4(0.f, 0.f, 0.f, 0.f);
#pragma unroll
        for (int sp = 0; sp < MSPLIT; sp++) {
            const int row = (h * MSPLIT + sp) * NN + n;
            l += g_l[row];
            uint2 v = *(const uint2*)&g_numh[row * (FOUT / 2) + qc * 2];
            float2 lo = __half22float2(*(__half2*)&v.x);
            float2 hi = __half22float2(*(__half2*)&v.y);
            acc.x += lo.x; acc.y += lo.y; acc.z += hi.x; acc.w += hi.y;
        }
        float inv = 32.0f / l;
        r.x += acc.x * inv; r.y += acc.y * inv; r.z += acc.z * inv; r.w += acc.w * inv;
    }
    r.x *= 0.25f; r.y *= 0.25f; r.z *= 0.25f; r.w *= 0.25f;
    *(float4*)&out[n * FOUT + qc * 4] = r;
}

extern "C" void kernel_launch(void* const* d_in, const int* in_sizes, int n_in,
                              void* d_out, int out_size) {
    const float* X   = (const float*)d_in[0];
    const int*   A   = (const int*)d_in[1];
    const float* W   = (const float*)d_in[2];
    const float* b   = (const float*)d_in[3];
    const float* att = (const float*)d_in[4];
    float* out = (float*)d_out;

    k_pp<<<256 + NN / 2, 256>>>(A, X, W, b, att);
    k_attn<<<dim3(NN / RPB, MSPLIT, HEADS), 256>>>();
    k_comb<<<(NN * FOUT / 4) / 256, 256>>>(out);
}

// round 9
// speedup vs baseline: 1.1376x; 1.0608x over previous
#include <cuda_runtime.h>
#include <cuda_fp16.h>

#define NN 4096
#define FIN 128
#define FOUT 64
#define HEADS 4
#define MSPLIT 4
#define RPB 128          // n-rows per block in k_attn
#define MTILE 128        // m per smem tile

// Device scratch (allocation-free rule: __device__ globals)
__device__ unsigned g_H2[HEADS * (NN / 2) * FOUT];   // H pairs (2m,2m+1) as fp16x2
__device__ float2   g_EF[HEADS * NN];                // {exp(d), exp(0.01d)}
__device__ float    g_G[HEADS * NN];                 // exp(-0.99 s)
__device__ unsigned g_mask[NN * (NN / 32)];          // bit-packed A|diag, MMA-permuted
__device__ unsigned g_numh[HEADS * MSPLIT * NN * (FOUT / 2)];  // fp16x2, scaled 1/32
__device__ float    g_l[HEADS * MSPLIT * NN];

__device__ __forceinline__ unsigned hmul2u(unsigned a, unsigned b) {
    __half2 r = __hmul2(*(__half2*)&a, *(__half2*)&b);
    return *(unsigned*)&r;
}
__device__ __forceinline__ unsigned hmax2u(unsigned a, unsigned b) {
    __half2 r = __hmax2(*(__half2*)&a, *(__half2*)&b);
    return *(unsigned*)&r;
}
__device__ __forceinline__ unsigned pk2(float lo, float hi) {
    __half2 r = __floats2half2_rn(lo, hi);
    return *(unsigned*)&r;
}

__device__ __forceinline__ void mma_f16(float c[4], const unsigned a[4],
                                        unsigned b0, unsigned b1) {
    asm volatile(
        "mma.sync.aligned.m16n8k16.row.col.f32.f16.f16.f32 "
        "{%0,%1,%2,%3}, {%4,%5,%6,%7}, {%8,%9}, {%0,%1,%2,%3};\n"
        : "+f"(c[0]), "+f"(c[1]), "+f"(c[2]), "+f"(c[3])
        : "r"(a[0]), "r"(a[1]), "r"(a[2]), "r"(a[3]), "r"(b0), "r"(b1));
}

// ---------------------------------------------------------------------------
// Kernel 1: merged projection (blocks 0..255) + adjacency bit-pack (blocks
// 256..). Pack is WARP-COALESCED: lane l loads int4 at col 4l (warp = 512
// contiguous bytes), builds its 4 permuted bits in-register, 8-lane REDUX.OR
// assembles each 32-col mask word. Bit layout identical to prior rounds:
// word bit (16hh+4tt+dd) = adjacency col (16hh + 2tt + (dd&1) + 8*(dd>>1)).
// ---------------------------------------------------------------------------
__global__ void __launch_bounds__(256) k_pp(const int* __restrict__ A,
                                            const float* __restrict__ X,
                                            const float* __restrict__ W,
                                            const float* __restrict__ b,
                                            const float* __restrict__ att) {
    __shared__ __align__(16) float XsT[64][68];   // [k][n-row]
    __shared__ __align__(16) float WsT[64][68];   // [k][o-row]
    const int t = threadIdx.x;

    if (blockIdx.x >= 256) {
        const int row  = blockIdx.x - 256;
        const int warp = t >> 5, lane = t & 31;
        const int j    = lane & 7;                 // position within 8-lane group
        const int w    = lane >> 3;                // word within 128-col chunk
        const int base = 16 * (j >> 2) + 8 * (j & 1) + 2 * ((j >> 1) & 1);
        const unsigned submask = 0xFFu << (w << 3);
#pragma unroll
        for (int it = 0; it < 4; it++) {
            const int chunk = it * 8 + warp;       // 0..31 (128 cols each)
            const int col0  = chunk * 128 + lane * 4;
            int4 a4 = *(const int4*)&A[row * NN + col0];
            unsigned p0 = (a4.x > 0) || (col0 == row);
            unsigned p1 = (a4.y > 0) || (col0 + 1 == row);
            unsigned p2 = (a4.z > 0) || (col0 + 2 == row);
            unsigned p3 = (a4.w > 0) || (col0 + 3 == row);
            unsigned contrib = (p0 | (p1 << 1) | (p2 << 4) | (p3 << 5)) << base;
            unsigned word = __reduce_or_sync(submask, contrib);
            if (j == 0) g_mask[row * (NN / 32) + chunk * 4 + w] = word;
        }
        return;
    }

    // ---- projection + fused per-node scores/exp factors
    const int h  = blockIdx.x >> 6;
    const int n0 = (blockIdx.x & 63) * 64;
    const int ty = t >> 4, tx = t & 15;

    float acc[4][4] = {};

    for (int kc = 0; kc < FIN; kc += 64) {
        __syncthreads();
#pragma unroll
        for (int u = 0; u < 4; u++) {
            int idx = t + 256 * u;
            int r = idx >> 4, q = (idx & 15) * 4;
            float4 xv = *(const float4*)&X[(n0 + r) * FIN + kc + q];
            XsT[q + 0][r] = xv.x; XsT[q + 1][r] = xv.y;
            XsT[q + 2][r] = xv.z; XsT[q + 3][r] = xv.w;
            float4 wv = *(const float4*)&W[(h * FOUT + r) * FIN + kc + q];
            WsT[q + 0][r] = wv.x; WsT[q + 1][r] = wv.y;
            WsT[q + 2][r] = wv.z; WsT[q + 3][r] = wv.w;
        }
        __syncthreads();
#pragma unroll 8
        for (int k = 0; k < 64; k++) {
            float4 av = *(const float4*)&XsT[k][ty * 4];
            float4 bv = *(const float4*)&WsT[k][tx * 4];
            acc[0][0] += av.x * bv.x; acc[0][1] += av.x * bv.y; acc[0][2] += av.x * bv.z; acc[0][3] += av.x * bv.w;
            acc[1][0] += av.y * bv.x; acc[1][1] += av.y * bv.y; acc[1][2] += av.y * bv.z; acc[1][3] += av.y * bv.w;
            acc[2][0] += av.z * bv.x; acc[2][1] += av.z * bv.y; acc[2][2] += av.z * bv.z; acc[2][3] += av.z * bv.w;
            acc[3][0] += av.w * bv.x; acc[3][1] += av.w * bv.y; acc[3][2] += av.w * bv.z; acc[3][3] += av.w * bv.w;
        }
    }

    float bb[4], as4[4], ad4[4];
#pragma unroll
    for (int j = 0; j < 4; j++) {
        bb[j]  = b[h * FOUT + tx * 4 + j];
        as4[j] = att[h * 2 * FOUT + tx * 4 + j];
        ad4[j] = att[h * 2 * FOUT + FOUT + tx * 4 + j];
    }
    float hv[4][4];
#pragma unroll
    for (int i = 0; i < 4; i++) {
        int n = n0 + ty * 4 + i;
        float s = 0.f, d = 0.f;
#pragma unroll
        for (int j = 0; j < 4; j++) {
            hv[i][j] = acc[i][j] + bb[j];
            s += hv[i][j] * as4[j];
            d += hv[i][j] * ad4[j];
        }
#pragma unroll
        for (int off = 8; off > 0; off >>= 1) {
            s += __shfl_xor_sync(0xffffffffu, s, off);
            d += __shfl_xor_sync(0xffffffffu, d, off);
        }
        if (tx == 0) {
            g_EF[h * NN + n] = make_float2(__expf(d), __expf(0.01f * d));
            g_G[h * NN + n]  = __expf(-0.99f * s);
        }
    }
    // write H as pair-packed fp16x2: g_H2[h][n/2][col]
#pragma unroll
    for (int i = 0; i < 4; i += 2) {
        int np = (n0 + ty * 4 + i) >> 1;
        uint4 pk = make_uint4(pk2(hv[i][0], hv[i + 1][0]), pk2(hv[i][1], hv[i + 1][1]),
                              pk2(hv[i][2], hv[i + 1][2]), pk2(hv[i][3], hv[i + 1][3]));
        *(uint4*)&g_H2[(h * (NN / 2) + np) * FOUT + tx * 4] = pk;
    }
}

// ---------------------------------------------------------------------------
// Kernel 2: fp16 tensor-core PV.  p = adj * max(E_m, F_m*G_n)  (exact
// leaky_relu branch select). l via ones-column MMA.
// block = 256 thr (8 warps x 16 rows); grid (32, MSPLIT, HEADS)
// ---------------------------------------------------------------------------
__global__ void __launch_bounds__(256) k_attn() {
    __shared__ unsigned Hs2[MTILE / 2][72];     // H pairs as fp16x2
    __shared__ uint2    dEF2s[MTILE / 2];       // {E2, F2} fp16x2 pairs
    __shared__ unsigned maskS[RPB][MTILE / 32];

    const int h  = blockIdx.z;
    const int sp = blockIdx.y;
    const int n0 = blockIdx.x * RPB;
    const int t  = threadIdx.x;
    const int warp = t >> 5, lane = t & 31;
    const int g = lane >> 2, tt = lane & 3;
    const int wrow = warp * 16;
    const unsigned ONES2 = 0x3C003C00u;

    unsigned G2u[2];
#pragma unroll
    for (int j = 0; j < 2; j++) {
        float gv = g_G[h * NN + n0 + wrow + g + 8 * j];
        G2u[j] = pk2(gv, gv);
    }

    float cacc[8][4] = {};
    float lacc[4] = {0.f, 0.f, 0.f, 0.f};

    const int mbase = sp * (NN / MSPLIT);

    for (int mt = 0; mt < NN / MSPLIT; mt += MTILE) {
        const int mb = mbase + mt;
        __syncthreads();
#pragma unroll
        for (int u = 0; u < 4; u++) {
            int id = t + 256 * u;
            int mp = id >> 4, q = (id & 15) << 2;
            *(uint4*)&Hs2[mp][q] =
                *(const uint4*)&g_H2[(h * (NN / 2) + (mb >> 1) + mp) * FOUT + q];
        }
        if (t < 64) {
            float2 v0 = g_EF[h * NN + mb + 2 * t];
            float2 v1 = g_EF[h * NN + mb + 2 * t + 1];
            dEF2s[t] = make_uint2(pk2(v0.x, v1.x), pk2(v0.y, v1.y));
        }
        if (t < RPB)
            *(uint4*)&maskS[t][0] =
                *(const uint4*)&g_mask[(n0 + t) * (NN / 32) + (mb >> 5)];
        __syncthreads();

#pragma unroll
        for (int cc = 0; cc < 8; cc++) {
            const uint2 ef0 = dEF2s[cc * 8 + tt];
            const uint2 ef1 = dEF2s[cc * 8 + tt + 4];
            unsigned pa[4];
#pragma unroll
            for (int j = 0; j < 2; j++) {
                unsigned w = maskS[wrow + g + 8 * j][cc >> 1];
                unsigned nib = (w >> (((cc & 1) << 4) + (tt << 2))) & 0xFu;
                unsigned am0 = (nib & 1u) * 0x3C00u + (nib & 2u) * 0x1E000000u;
                unsigned am1 = (nib & 4u) * 0x0F00u + (nib & 8u) * 0x07800000u;
                pa[j]     = hmul2u(hmax2u(ef0.x, hmul2u(ef0.y, G2u[j])), am0);
                pa[2 + j] = hmul2u(hmax2u(ef1.x, hmul2u(ef1.y, G2u[j])), am1);
            }
#pragma unroll
            for (int jc = 0; jc < 8; jc++) {
                unsigned b0 = Hs2[cc * 8 + tt][jc * 8 + g];
                unsigned b1 = Hs2[cc * 8 + tt + 4][jc * 8 + g];
                mma_f16(cacc[jc], pa, b0, b1);
            }
            mma_f16(lacc, pa, ONES2, ONES2);
        }
    }

    const int base = (h * MSPLIT + sp) * NN;
    if (tt == 0) {
        g_l[base + n0 + wrow + g]     = lacc[0];
        g_l[base + n0 + wrow + g + 8] = lacc[2];
    }
    const float S = 1.0f / 32.0f;
    const int r0 = base + n0 + wrow + g;
#pragma unroll
    for (int jc = 0; jc < 8; jc++) {
        g_numh[r0 * (FOUT / 2) + jc * 4 + tt] = pk2(cacc[jc][0] * S, cacc[jc][1] * S);
        g_numh[(r0 + 8) * (FOUT / 2) + jc * 4 + tt] = pk2(cacc[jc][2] * S, cacc[jc][3] * S);
    }
}

// ---------------------------------------------------------------------------
// Kernel 3: combine m-splits and heads
// ---------------------------------------------------------------------------
__global__ void k_comb(float* __restrict__ out) {
    const int t = blockIdx.x * 256 + threadIdx.x;
    const int n = t >> 4;
    const int qc = t & 15;
    float4 r = make_float4(0.f, 0.f, 0.f, 0.f);
#pragma unroll
    for (int h = 0; h < HEADS; h++) {
        float l = 0.0f;
        float4 acc = make_float4(0.f, 0.f, 0.f, 0.f);
#pragma unroll
        for (int sp = 0; sp < MSPLIT; sp++) {
            const int row = (h * MSPLIT + sp) * NN + n;
            l += g_l[row];
            uint2 v = *(const uint2*)&g_numh[row * (FOUT / 2) + qc * 2];
            float2 lo = __half22float2(*(__half2*)&v.x);
            float2 hi = __half22float2(*(__half2*)&v.y);
            acc.x += lo.x; acc.y += lo.y; acc.z += hi.x; acc.w += hi.y;
        }
        float inv = 32.0f / l;
        r.x += acc.x * inv; r.y += acc.y * inv; r.z += acc.z * inv; r.w += acc.w * inv;
    }
    r.x *= 0.25f; r.y *= 0.25f; r.z *= 0.25f; r.w *= 0.25f;
    *(float4*)&out[n * FOUT + qc * 4] = r;
}

extern "C" void kernel_launch(void* const* d_in, const int* in_sizes, int n_in,
                              void* d_out, int out_size) {
    const float* X   = (const float*)d_in[0];
    const int*   A   = (const int*)d_in[1];
    const float* W   = (const float*)d_in[2];
    const float* b   = (const float*)d_in[3];
    const float* att = (const float*)d_in[4];
    float* out = (float*)d_out;

    k_pp<<<256 + NN, 256>>>(A, X, W, b, att);
    k_attn<<<dim3(NN / RPB, MSPLIT, HEADS), 256>>>();
    k_comb<<<(NN * FOUT / 4) / 256, 256>>>(out);
}